// round 5
// baseline (speedup 1.0000x reference)
#include <cuda_runtime.h>

#define NN 100000
#define EE 1600000
#define HF 128
#define GG 128
#define LL 4
#define EPS_BN 1e-5f
#define BM 128
#define BK 32
#define ASTRIDE 132

// ---------------- scratch (static device globals; no allocs allowed) ----------
__device__ float g_h[(size_t)NN * HF];    // current layer input  (51.2 MB)
__device__ float g_agg[(size_t)NN * HF];  // neighbor sums        (51.2 MB)
__device__ float g_rst[(size_t)NN * HF];  // pre-BN layer output  (51.2 MB)
__device__ float g_deg[NN];
__device__ float g_rdeg[NN];
__device__ float g_cnt[GG];
__device__ float g_stats[LL * 2 * HF];    // per-layer [sum | sumsq]
__device__ float g_norm[LL * 2 * HF];     // per-layer [scale | shift]
__device__ float g_pool[GG * LL * HF];    // graph pooling accumulator [G,512]

__device__ __forceinline__ void red_add_v4(float* a, float4 v) {
    asm volatile("red.global.add.v4.f32 [%0], {%1,%2,%3,%4};"
                 :: "l"(a), "f"(v.x), "f"(v.y), "f"(v.z), "f"(v.w) : "memory");
}

// ---------------- init: h0 = emb[in_feat] -------------------------------------
__global__ void k_init(const int* __restrict__ feat, const float* __restrict__ emb) {
    int idx = blockIdx.x * blockDim.x + threadIdx.x;  // over NN*32 (float4 granules)
    if (idx >= NN * 32) return;
    int node = idx >> 5, q = idx & 31;
    int f = __ldg(&feat[node]);
    float4 v = __ldg((const float4*)(emb + (size_t)f * HF) + q);
    *((float4*)(g_h + (size_t)node * HF) + q) = v;
}

// ---------------- in-degree ----------------------------------------------------
__global__ void k_deg(const int* __restrict__ dst) {
    int e = blockIdx.x * blockDim.x + threadIdx.x;
    if (e < EE) atomicAdd(&g_deg[__ldg(&dst[e])], 1.0f);
}

// ---------------- graph node counts (smem histogram; graph_ids ~sorted) --------
__global__ void k_cnt(const int* __restrict__ gid) {
    __shared__ float sh[GG];
    int t = threadIdx.x;
    if (t < GG) sh[t] = 0.f;
    __syncthreads();
    int i = blockIdx.x * blockDim.x + t;
    if (i < NN) atomicAdd(&sh[__ldg(&gid[i])], 1.0f);
    __syncthreads();
    if (t < GG && sh[t] != 0.f) atomicAdd(&g_cnt[t], sh[t]);
}

__global__ void k_rdeg() {
    int i = blockIdx.x * blockDim.x + threadIdx.x;
    if (i < NN) g_rdeg[i] = 1.0f / fmaxf(g_deg[i], 1.0f);
}

// ---------------- aggregation: warp per edge, float4 lanes, vector red ---------
__global__ void k_agg(const int* __restrict__ src, const int* __restrict__ dst) {
    int w = (blockIdx.x * blockDim.x + threadIdx.x) >> 5;
    if (w >= EE) return;
    int lane = threadIdx.x & 31;
    int s = __ldg(&src[w]);
    int d = __ldg(&dst[w]);
    float4 v = *((const float4*)(g_h + (size_t)s * HF) + lane);
    red_add_v4((float*)((float4*)(g_agg + (size_t)d * HF) + lane), v);
}

// ---------------- fused GEMM: rst = h@Ws + (agg*rdeg)@Wn + b, PReLU, stats -----
__global__ __launch_bounds__(256) void k_gemm(
    const float* __restrict__ Ws, const float* __restrict__ Wn,
    const float* __restrict__ bias, const float* __restrict__ pw, int l)
{
    __shared__ float As[BK * ASTRIDE];  // 32 x (128+4) transposed A tile
    __shared__ float Bs[BK * HF];       // 32 x 128 W tile (reused for reductions)

    int t = threadIdx.x;
    int tx = t & 15, ty = t >> 4;
    int row0 = blockIdx.x * BM;

    float acc[8][8];
    #pragma unroll
    for (int r = 0; r < 8; r++)
        #pragma unroll
        for (int c = 0; c < 8; c++) acc[r][c] = 0.f;

    #pragma unroll
    for (int phase = 0; phase < 2; phase++) {
        const float* A = phase ? g_agg : g_h;
        const float* W = phase ? Wn : Ws;
        for (int k0 = 0; k0 < HF; k0 += BK) {
            // --- A tile: 128 rows x 32 k, transposed into As[k][m] ---
            #pragma unroll
            for (int i = 0; i < 4; i++) {
                int j = i * 256 + t;      // 0..1023 float4s
                int m = j >> 3;           // row within tile
                int kk = (j & 7) << 2;    // k offset within tile
                int row = row0 + m;
                float4 a = make_float4(0.f, 0.f, 0.f, 0.f);
                float s = 0.f;
                if (row < NN) {
                    a = __ldg((const float4*)(A + (size_t)row * HF + k0) + (j & 7));
                    s = phase ? __ldg(&g_rdeg[row]) : 1.0f;
                }
                As[(kk + 0) * ASTRIDE + m] = a.x * s;
                As[(kk + 1) * ASTRIDE + m] = a.y * s;
                As[(kk + 2) * ASTRIDE + m] = a.z * s;
                As[(kk + 3) * ASTRIDE + m] = a.w * s;
            }
            // --- B tile: 32 k x 128 n, straight copy ---
            #pragma unroll
            for (int i = 0; i < 4; i++) {
                int j = i * 256 + t;
                int kk = j >> 5;
                int c4 = j & 31;
                float4 b4 = __ldg((const float4*)(W + (size_t)(k0 + kk) * HF) + c4);
                *((float4*)(Bs + kk * HF) + c4) = b4;
            }
            __syncthreads();
            #pragma unroll
            for (int kk = 0; kk < BK; kk++) {
                float4 a0 = *(const float4*)&As[kk * ASTRIDE + ty * 8];
                float4 a1 = *(const float4*)&As[kk * ASTRIDE + ty * 8 + 4];
                float4 b0 = *(const float4*)&Bs[kk * HF + tx * 8];
                float4 b1 = *(const float4*)&Bs[kk * HF + tx * 8 + 4];
                float ar[8] = {a0.x, a0.y, a0.z, a0.w, a1.x, a1.y, a1.z, a1.w};
                float br[8] = {b0.x, b0.y, b0.z, b0.w, b1.x, b1.y, b1.z, b1.w};
                #pragma unroll
                for (int r = 0; r < 8; r++)
                    #pragma unroll
                    for (int c = 0; c < 8; c++)
                        acc[r][c] = fmaf(ar[r], br[c], acc[r][c]);
            }
            __syncthreads();
        }
    }

    // --- epilogue: bias, PReLU, store rst, per-channel partial sums -------------
    float bc[8], pc[8];
    #pragma unroll
    for (int c = 0; c < 8; c++) {
        bc[c] = __ldg(&bias[tx * 8 + c]);
        pc[c] = __ldg(&pw[tx * 8 + c]);
    }
    float ps[8] = {0}, pq[8] = {0};
    #pragma unroll
    for (int r = 0; r < 8; r++) {
        int row = row0 + ty * 8 + r;
        if (row < NN) {
            float v[8];
            #pragma unroll
            for (int c = 0; c < 8; c++) {
                float x = acc[r][c] + bc[c];
                x = x > 0.f ? x : pc[c] * x;
                v[c] = x;
                ps[c] += x;
                pq[c] += x * x;
            }
            float4* o = (float4*)(g_rst + (size_t)row * HF + tx * 8);
            o[0] = make_float4(v[0], v[1], v[2], v[3]);
            o[1] = make_float4(v[4], v[5], v[6], v[7]);
        }
    }
    __syncthreads();   // done with Bs as W tile
    #pragma unroll
    for (int c = 0; c < 8; c++) {
        Bs[ty * HF + tx * 8 + c] = ps[c];
        Bs[2048 + ty * HF + tx * 8 + c] = pq[c];
    }
    __syncthreads();
    if (t < HF) {
        float s = 0.f, q = 0.f;
        #pragma unroll
        for (int r = 0; r < 16; r++) {
            s += Bs[r * HF + t];
            q += Bs[2048 + r * HF + t];
        }
        atomicAdd(&g_stats[l * 2 * HF + t], s);
        atomicAdd(&g_stats[l * 2 * HF + HF + t], q);
    }
}

// ---------------- BN stats finalize: scale/shift per channel -------------------
__global__ void k_finalize(const float* __restrict__ gamma,
                           const float* __restrict__ beta, int l) {
    int c = threadIdx.x;
    float s = g_stats[l * 2 * HF + c];
    float q = g_stats[l * 2 * HF + HF + c];
    const float inv_n = 1.0f / (float)NN;
    float mu = s * inv_n;
    float var = fmaf(-mu, mu, q * inv_n);
    float rs = rsqrtf(var + EPS_BN);
    float sc = __ldg(&gamma[c]) * rs;
    float sh = fmaf(-mu, sc, __ldg(&beta[c]));
    g_norm[l * 2 * HF + c] = sc;
    g_norm[l * 2 * HF + HF + c] = sh;
}

// ---------------- apply BN, write h_next, accumulate graph pool ----------------
__global__ void k_apply(const int* __restrict__ gid, int l) {
    int w = (blockIdx.x * blockDim.x + threadIdx.x) >> 5;
    if (w >= NN) return;
    int lane = threadIdx.x & 31;
    float4 v = *((const float4*)(g_rst + (size_t)w * HF) + lane);
    float4 sc = *((const float4*)(g_norm + l * 2 * HF) + lane);
    float4 sh = *((const float4*)(g_norm + l * 2 * HF + HF) + lane);
    v.x = fmaf(v.x, sc.x, sh.x);
    v.y = fmaf(v.y, sc.y, sh.y);
    v.z = fmaf(v.z, sc.z, sh.z);
    v.w = fmaf(v.w, sc.w, sh.w);
    *((float4*)(g_h + (size_t)w * HF) + lane) = v;
    int g = __ldg(&gid[w]);
    red_add_v4((float*)((float4*)(g_pool + (size_t)g * (LL * HF) + l * HF) + lane), v);
}

// ---------------- final: divide pool by graph counts ---------------------------
__global__ void k_out(float* __restrict__ out) {
    int i = blockIdx.x * blockDim.x + threadIdx.x;
    if (i < GG * LL * HF) {
        int g = i >> 9;  // / 512
        out[i] = g_pool[i] / fmaxf(g_cnt[g], 1.0f);
    }
}

// ---------------- launch --------------------------------------------------------
extern "C" void kernel_launch(void* const* d_in, const int* in_sizes, int n_in,
                              void* d_out, int out_size) {
    const int*   in_feat = (const int*)d_in[0];
    const int*   src     = (const int*)d_in[1];
    const int*   dst     = (const int*)d_in[2];
    const int*   gid     = (const int*)d_in[3];
    const float* emb     = (const float*)d_in[4];
    const float* W_self  = (const float*)d_in[5];
    const float* W_neigh = (const float*)d_in[6];
    const float* bias    = (const float*)d_in[7];
    const float* gamma   = (const float*)d_in[8];
    const float* beta    = (const float*)d_in[9];
    const float* prelu   = (const float*)d_in[10];

    void *p_agg, *p_deg, *p_cnt, *p_pool, *p_stats;
    cudaGetSymbolAddress(&p_agg, g_agg);
    cudaGetSymbolAddress(&p_deg, g_deg);
    cudaGetSymbolAddress(&p_cnt, g_cnt);
    cudaGetSymbolAddress(&p_pool, g_pool);
    cudaGetSymbolAddress(&p_stats, g_stats);

    cudaMemsetAsync(p_deg, 0, NN * sizeof(float));
    cudaMemsetAsync(p_cnt, 0, GG * sizeof(float));
    cudaMemsetAsync(p_pool, 0, (size_t)GG * LL * HF * sizeof(float));
    cudaMemsetAsync(p_stats, 0, (size_t)LL * 2 * HF * sizeof(float));

    k_init<<<(NN * 32 + 255) / 256, 256>>>(in_feat, emb);
    k_deg<<<(EE + 255) / 256, 256>>>(dst);
    k_cnt<<<(NN + 255) / 256, 256>>>(gid);
    k_rdeg<<<(NN + 255) / 256, 256>>>();

    for (int l = 0; l < LL; l++) {
        cudaMemsetAsync(p_agg, 0, (size_t)NN * HF * sizeof(float));
        k_agg<<<(EE + 7) / 8, 256>>>(src, dst);
        k_gemm<<<(NN + BM - 1) / BM, 256>>>(W_self + (size_t)l * HF * HF,
                                            W_neigh + (size_t)l * HF * HF,
                                            bias + l * HF, prelu + l * HF, l);
        k_finalize<<<1, HF>>>(gamma + l * HF, beta + l * HF, l);
        k_apply<<<(NN * 32 + 255) / 256, 256>>>(gid, l);
    }
    k_out<<<(GG * LL * HF + 255) / 256, 256>>>((float*)d_out);
}

// round 6
// speedup vs baseline: 1.5606x; 1.5606x over previous
#include <cuda_runtime.h>

#define NN 100000
#define EE 1600000
#define HF 128
#define GG 128
#define LL 4
#define EPS_BN 1e-5f
#define BM 128
#define BK 32
#define ASTRIDE 132
#define SCAN_B 512
#define NB ((NN + SCAN_B - 1) / SCAN_B)   // 196

// ---------------- scratch (static device globals; no allocs allowed) ----------
__device__ float g_h[(size_t)NN * HF];    // current layer input  (51.2 MB)
__device__ float g_agg[(size_t)NN * HF];  // normalized neighbor means
__device__ float g_rst[(size_t)NN * HF];  // pre-BN layer output
__device__ float g_rdeg[NN];
__device__ float g_cnt[GG];
__device__ float g_stats[LL * 2 * HF];    // per-layer [sum | sumsq]
__device__ float g_norm[LL * 2 * HF];     // per-layer [scale | shift]
__device__ float g_pool[GG * LL * HF];    // graph pooling accumulator [G,512]
// CSR scratch
__device__ int g_cnt_i[NN];               // in-degree (int)
__device__ int g_rowptr[NN];              // exclusive prefix of degrees
__device__ int g_cur[NN];                 // scatter cursors
__device__ int g_bsum[SCAN_B];            // block sums for scan
__device__ int g_eidx[EE];                // CSR column indices (src per dst)

__device__ __forceinline__ void red_add_v4(float* a, float4 v) {
    asm volatile("red.global.add.v4.f32 [%0], {%1,%2,%3,%4};"
                 :: "l"(a), "f"(v.x), "f"(v.y), "f"(v.z), "f"(v.w) : "memory");
}

// ---------------- init: h0 = emb[in_feat] -------------------------------------
__global__ void k_init(const int* __restrict__ feat, const float* __restrict__ emb) {
    int idx = blockIdx.x * blockDim.x + threadIdx.x;
    if (idx >= NN * 32) return;
    int node = idx >> 5, q = idx & 31;
    int f = __ldg(&feat[node]);
    float4 v = __ldg((const float4*)(emb + (size_t)f * HF) + q);
    *((float4*)(g_h + (size_t)node * HF) + q) = v;
}

// ---------------- CSR build ----------------------------------------------------
__global__ void k_hist(const int* __restrict__ dst) {
    int e = blockIdx.x * blockDim.x + threadIdx.x;
    if (e < EE) atomicAdd(&g_cnt_i[__ldg(&dst[e])], 1);
}

__global__ void k_scan1() {
    __shared__ int sh[SCAN_B];
    int t = threadIdx.x;
    int i = blockIdx.x * SCAN_B + t;
    int v = (i < NN) ? g_cnt_i[i] : 0;
    sh[t] = v;
    __syncthreads();
    #pragma unroll
    for (int off = 1; off < SCAN_B; off <<= 1) {
        int x = (t >= off) ? sh[t - off] : 0;
        __syncthreads();
        sh[t] += x;
        __syncthreads();
    }
    if (i < NN) g_rowptr[i] = sh[t] - v;       // exclusive
    if (t == SCAN_B - 1) g_bsum[blockIdx.x] = sh[t];
}

__global__ void k_scan2() {
    __shared__ int sh[256];
    int t = threadIdx.x;
    int v = (t < NB) ? g_bsum[t] : 0;
    sh[t] = v;
    __syncthreads();
    #pragma unroll
    for (int off = 1; off < 256; off <<= 1) {
        int x = (t >= off) ? sh[t - off] : 0;
        __syncthreads();
        sh[t] += x;
        __syncthreads();
    }
    if (t < NB) g_bsum[t] = sh[t] - v;         // exclusive
}

__global__ void k_scan3() {
    int i = blockIdx.x * blockDim.x + threadIdx.x;
    if (i >= NN) return;
    int base = g_rowptr[i] + g_bsum[i / SCAN_B];
    g_rowptr[i] = base;
    g_cur[i] = base;
    g_rdeg[i] = 1.0f / fmaxf((float)g_cnt_i[i], 1.0f);
}

__global__ void k_scatter(const int* __restrict__ src, const int* __restrict__ dst) {
    int e = blockIdx.x * blockDim.x + threadIdx.x;
    if (e >= EE) return;
    int d = __ldg(&dst[e]);
    int pos = atomicAdd(&g_cur[d], 1);
    g_eidx[pos] = __ldg(&src[e]);
}

// ---------------- graph node counts (smem histogram; graph_ids sorted) --------
__global__ void k_cnt(const int* __restrict__ gid) {
    __shared__ float sh[GG];
    int t = threadIdx.x;
    if (t < GG) sh[t] = 0.f;
    __syncthreads();
    int i = blockIdx.x * blockDim.x + t;
    if (i < NN) atomicAdd(&sh[__ldg(&gid[i])], 1.0f);
    __syncthreads();
    if (t < GG && sh[t] != 0.f) atomicAdd(&g_cnt[t], sh[t]);
}

// ---------------- aggregation: CSR gather, warp per node, atomic-free ---------
__global__ __launch_bounds__(256) void k_gather() {
    int w = (blockIdx.x * blockDim.x + threadIdx.x) >> 5;
    if (w >= NN) return;
    int lane = threadIdx.x & 31;
    int beg = __ldg(&g_rowptr[w]);
    int cnt = __ldg(&g_cnt_i[w]);
    float4 a0 = make_float4(0.f, 0.f, 0.f, 0.f);
    float4 a1 = make_float4(0.f, 0.f, 0.f, 0.f);
    for (int base = 0; base < cnt; base += 32) {
        int idx = (base + lane < cnt) ? __ldg(&g_eidx[beg + base + lane]) : 0;
        int m = min(32, cnt - base);
        int j = 0;
        for (; j + 1 < m; j += 2) {
            int s0 = __shfl_sync(0xffffffffu, idx, j);
            int s1 = __shfl_sync(0xffffffffu, idx, j + 1);
            float4 v0 = __ldg((const float4*)(g_h + (size_t)s0 * HF) + lane);
            float4 v1 = __ldg((const float4*)(g_h + (size_t)s1 * HF) + lane);
            a0.x += v0.x; a0.y += v0.y; a0.z += v0.z; a0.w += v0.w;
            a1.x += v1.x; a1.y += v1.y; a1.z += v1.z; a1.w += v1.w;
        }
        if (j < m) {
            int s0 = __shfl_sync(0xffffffffu, idx, j);
            float4 v0 = __ldg((const float4*)(g_h + (size_t)s0 * HF) + lane);
            a0.x += v0.x; a0.y += v0.y; a0.z += v0.z; a0.w += v0.w;
        }
    }
    float r = __ldg(&g_rdeg[w]);
    float4 o;
    o.x = (a0.x + a1.x) * r;
    o.y = (a0.y + a1.y) * r;
    o.z = (a0.z + a1.z) * r;
    o.w = (a0.w + a1.w) * r;
    *((float4*)(g_agg + (size_t)w * HF) + lane) = o;
}

// ---------------- fused GEMM: rst = h@Ws + agg@Wn + b, PReLU, stats ------------
__global__ __launch_bounds__(256) void k_gemm(
    const float* __restrict__ Ws, const float* __restrict__ Wn,
    const float* __restrict__ bias, const float* __restrict__ pw, int l)
{
    __shared__ float As[BK * ASTRIDE];
    __shared__ float Bs[BK * HF];

    int t = threadIdx.x;
    int tx = t & 15, ty = t >> 4;
    int row0 = blockIdx.x * BM;

    float acc[8][8];
    #pragma unroll
    for (int r = 0; r < 8; r++)
        #pragma unroll
        for (int c = 0; c < 8; c++) acc[r][c] = 0.f;

    #pragma unroll
    for (int phase = 0; phase < 2; phase++) {
        const float* A = phase ? g_agg : g_h;
        const float* W = phase ? Wn : Ws;
        for (int k0 = 0; k0 < HF; k0 += BK) {
            #pragma unroll
            for (int i = 0; i < 4; i++) {
                int j = i * 256 + t;
                int m = j >> 3;
                int kk = (j & 7) << 2;
                int row = row0 + m;
                float4 a = make_float4(0.f, 0.f, 0.f, 0.f);
                if (row < NN)
                    a = __ldg((const float4*)(A + (size_t)row * HF + k0) + (j & 7));
                As[(kk + 0) * ASTRIDE + m] = a.x;
                As[(kk + 1) * ASTRIDE + m] = a.y;
                As[(kk + 2) * ASTRIDE + m] = a.z;
                As[(kk + 3) * ASTRIDE + m] = a.w;
            }
            #pragma unroll
            for (int i = 0; i < 4; i++) {
                int j = i * 256 + t;
                int kk = j >> 5;
                int c4 = j & 31;
                float4 b4 = __ldg((const float4*)(W + (size_t)(k0 + kk) * HF) + c4);
                *((float4*)(Bs + kk * HF) + c4) = b4;
            }
            __syncthreads();
            #pragma unroll
            for (int kk = 0; kk < BK; kk++) {
                float4 a0 = *(const float4*)&As[kk * ASTRIDE + ty * 8];
                float4 a1 = *(const float4*)&As[kk * ASTRIDE + ty * 8 + 4];
                float4 b0 = *(const float4*)&Bs[kk * HF + tx * 8];
                float4 b1 = *(const float4*)&Bs[kk * HF + tx * 8 + 4];
                float ar[8] = {a0.x, a0.y, a0.z, a0.w, a1.x, a1.y, a1.z, a1.w};
                float br[8] = {b0.x, b0.y, b0.z, b0.w, b1.x, b1.y, b1.z, b1.w};
                #pragma unroll
                for (int r = 0; r < 8; r++)
                    #pragma unroll
                    for (int c = 0; c < 8; c++)
                        acc[r][c] = fmaf(ar[r], br[c], acc[r][c]);
            }
            __syncthreads();
        }
    }

    float bc[8], pc[8];
    #pragma unroll
    for (int c = 0; c < 8; c++) {
        bc[c] = __ldg(&bias[tx * 8 + c]);
        pc[c] = __ldg(&pw[tx * 8 + c]);
    }
    float ps[8] = {0}, pq[8] = {0};
    #pragma unroll
    for (int r = 0; r < 8; r++) {
        int row = row0 + ty * 8 + r;
        if (row < NN) {
            float v[8];
            #pragma unroll
            for (int c = 0; c < 8; c++) {
                float x = acc[r][c] + bc[c];
                x = x > 0.f ? x : pc[c] * x;
                v[c] = x;
                ps[c] += x;
                pq[c] += x * x;
            }
            float4* o = (float4*)(g_rst + (size_t)row * HF + tx * 8);
            o[0] = make_float4(v[0], v[1], v[2], v[3]);
            o[1] = make_float4(v[4], v[5], v[6], v[7]);
        }
    }
    __syncthreads();
    #pragma unroll
    for (int c = 0; c < 8; c++) {
        Bs[ty * HF + tx * 8 + c] = ps[c];
        Bs[2048 + ty * HF + tx * 8 + c] = pq[c];
    }
    __syncthreads();
    if (t < HF) {
        float s = 0.f, q = 0.f;
        #pragma unroll
        for (int r = 0; r < 16; r++) {
            s += Bs[r * HF + t];
            q += Bs[2048 + r * HF + t];
        }
        atomicAdd(&g_stats[l * 2 * HF + t], s);
        atomicAdd(&g_stats[l * 2 * HF + HF + t], q);
    }
}

// ---------------- BN stats finalize --------------------------------------------
__global__ void k_finalize(const float* __restrict__ gamma,
                           const float* __restrict__ beta, int l) {
    int c = threadIdx.x;
    float s = g_stats[l * 2 * HF + c];
    float q = g_stats[l * 2 * HF + HF + c];
    const float inv_n = 1.0f / (float)NN;
    float mu = s * inv_n;
    float var = fmaf(-mu, mu, q * inv_n);
    float rs = rsqrtf(var + EPS_BN);
    float sc = __ldg(&gamma[c]) * rs;
    float sh = fmaf(-mu, sc, __ldg(&beta[c]));
    g_norm[l * 2 * HF + c] = sc;
    g_norm[l * 2 * HF + HF + c] = sh;
}

// ---------------- apply BN, write h_next, pooled red with run-fusion -----------
// Warp handles 8 consecutive nodes; graph_ids sorted => locally accumulate the
// pool vector per graph-run, flush on id change (8x fewer red ops).
__global__ void k_apply(const int* __restrict__ gid, int l) {
    int w = (blockIdx.x * blockDim.x + threadIdx.x) >> 5;
    int n0 = w * 8;
    if (n0 >= NN) return;
    int lane = threadIdx.x & 31;
    float4 sc = *((const float4*)(g_norm + l * 2 * HF) + lane);
    float4 sh = *((const float4*)(g_norm + l * 2 * HF + HF) + lane);
    float4 acc = make_float4(0.f, 0.f, 0.f, 0.f);
    int cur = __ldg(&gid[n0]);
    int nend = min(n0 + 8, NN);
    for (int n = n0; n < nend; n++) {
        float4 v = *((const float4*)(g_rst + (size_t)n * HF) + lane);
        v.x = fmaf(v.x, sc.x, sh.x);
        v.y = fmaf(v.y, sc.y, sh.y);
        v.z = fmaf(v.z, sc.z, sh.z);
        v.w = fmaf(v.w, sc.w, sh.w);
        *((float4*)(g_h + (size_t)n * HF) + lane) = v;
        int g = __ldg(&gid[n]);
        if (g != cur) {
            red_add_v4((float*)((float4*)(g_pool + (size_t)cur * (LL * HF) + l * HF) + lane), acc);
            acc = make_float4(0.f, 0.f, 0.f, 0.f);
            cur = g;
        }
        acc.x += v.x; acc.y += v.y; acc.z += v.z; acc.w += v.w;
    }
    red_add_v4((float*)((float4*)(g_pool + (size_t)cur * (LL * HF) + l * HF) + lane), acc);
}

// ---------------- final: divide pool by graph counts ---------------------------
__global__ void k_out(float* __restrict__ out) {
    int i = blockIdx.x * blockDim.x + threadIdx.x;
    if (i < GG * LL * HF) {
        int g = i >> 9;
        out[i] = g_pool[i] / fmaxf(g_cnt[g], 1.0f);
    }
}

// ---------------- launch --------------------------------------------------------
extern "C" void kernel_launch(void* const* d_in, const int* in_sizes, int n_in,
                              void* d_out, int out_size) {
    const int*   in_feat = (const int*)d_in[0];
    const int*   src     = (const int*)d_in[1];
    const int*   dst     = (const int*)d_in[2];
    const int*   gid     = (const int*)d_in[3];
    const float* emb     = (const float*)d_in[4];
    const float* W_self  = (const float*)d_in[5];
    const float* W_neigh = (const float*)d_in[6];
    const float* bias    = (const float*)d_in[7];
    const float* gamma   = (const float*)d_in[8];
    const float* beta    = (const float*)d_in[9];
    const float* prelu   = (const float*)d_in[10];

    void *p_cnti, *p_cnt, *p_pool, *p_stats;
    cudaGetSymbolAddress(&p_cnti, g_cnt_i);
    cudaGetSymbolAddress(&p_cnt, g_cnt);
    cudaGetSymbolAddress(&p_pool, g_pool);
    cudaGetSymbolAddress(&p_stats, g_stats);

    cudaMemsetAsync(p_cnti, 0, NN * sizeof(int));
    cudaMemsetAsync(p_cnt, 0, GG * sizeof(float));
    cudaMemsetAsync(p_pool, 0, (size_t)GG * LL * HF * sizeof(float));
    cudaMemsetAsync(p_stats, 0, (size_t)LL * 2 * HF * sizeof(float));

    k_init<<<(NN * 32 + 255) / 256, 256>>>(in_feat, emb);
    // CSR build
    k_hist<<<(EE + 255) / 256, 256>>>(dst);
    k_scan1<<<NB, SCAN_B>>>();
    k_scan2<<<1, 256>>>();
    k_scan3<<<(NN + 255) / 256, 256>>>();
    k_scatter<<<(EE + 255) / 256, 256>>>(src, dst);
    k_cnt<<<(NN + 255) / 256, 256>>>(gid);

    for (int l = 0; l < LL; l++) {
        k_gather<<<(NN * 32 + 255) / 256, 256>>>();
        k_gemm<<<(NN + BM - 1) / BM, 256>>>(W_self + (size_t)l * HF * HF,
                                            W_neigh + (size_t)l * HF * HF,
                                            bias + l * HF, prelu + l * HF, l);
        k_finalize<<<1, HF>>>(gamma + l * HF, beta + l * HF, l);
        k_apply<<<(((NN + 7) / 8) * 32 + 255) / 256, 256>>>(gid, l);
    }
    k_out<<<(GG * LL * HF + 255) / 256, 256>>>((float*)d_out);
}